// round 1
// baseline (speedup 1.0000x reference)
#include <cuda_runtime.h>
#include <cuda_bf16.h>
#include <math.h>

// ---------------- problem dims ----------------
#define BB 2
#define LL 4096
#define DD 1024
#define NN 16
#define KK 4
#define MROWS (BB*LL)          // 8192
#define Y_ELEMS (BB*LL*DD)     // 8388608

// ---------------- scratch (device globals; no runtime alloc) -------------
__device__ float g_xssm[Y_ELEMS];
__device__ float g_gate[Y_ELEMS];   // silu(gate)
__device__ float g_xconv[Y_ELEMS];
__device__ float g_yg[Y_ELEMS];     // y * silu(gate)
__device__ float g_B[BB*LL*NN];
__device__ float g_C[BB*LL*NN];

// ---------------- SGEMM: C = A[M,K] @ B[K,N] + bias ----------------
// mode 0: plain store to C0[M,N]
// mode 1: split: cols [0,N/2) -> C0 raw, cols [N/2,N) -> C1 = silu(v)
#define BM 128
#define BN 128
#define BKd 8
#define TM 8
#define TN 8

__global__ __launch_bounds__(256, 2)
void sgemm_kernel(const float* __restrict__ A, const float* __restrict__ Bm,
                  const float* __restrict__ bias,
                  float* __restrict__ C0, float* __restrict__ C1,
                  int M, int N, int K, int mode)
{
    __shared__ float As[BKd][BM];
    __shared__ float Bs[BKd][BN];

    const int tid = threadIdx.x;
    const int row_c = blockIdx.y * BM;
    const int col_c = blockIdx.x * BN;

    const int a_row = tid >> 1;          // 0..127
    const int a_col = (tid & 1) * 4;     // 0 or 4
    const int b_row = tid >> 5;          // 0..7
    const int b_col = (tid & 31) * 4;    // 0..124

    const int ty = (tid >> 4) * TM;
    const int tx = (tid & 15) * TN;

    float acc[TM][TN];
    #pragma unroll
    for (int i = 0; i < TM; i++)
        #pragma unroll
        for (int j = 0; j < TN; j++) acc[i][j] = 0.0f;

    const float* Aptr = A + (size_t)row_c * K;
    const float* Bptr = Bm + col_c;

    for (int k0 = 0; k0 < K; k0 += BKd) {
        float4 a4 = *(const float4*)(Aptr + (size_t)a_row * K + k0 + a_col);
        As[a_col + 0][a_row] = a4.x;
        As[a_col + 1][a_row] = a4.y;
        As[a_col + 2][a_row] = a4.z;
        As[a_col + 3][a_row] = a4.w;
        float4 b4 = *(const float4*)(Bptr + (size_t)(k0 + b_row) * N + b_col);
        *(float4*)&Bs[b_row][b_col] = b4;
        __syncthreads();

        #pragma unroll
        for (int k = 0; k < BKd; k++) {
            float ar[TM], br[TN];
            #pragma unroll
            for (int i = 0; i < TM; i++) ar[i] = As[k][ty + i];
            #pragma unroll
            for (int j = 0; j < TN; j++) br[j] = Bs[k][tx + j];
            #pragma unroll
            for (int i = 0; i < TM; i++)
                #pragma unroll
                for (int j = 0; j < TN; j++)
                    acc[i][j] = fmaf(ar[i], br[j], acc[i][j]);
        }
        __syncthreads();
    }

    const int halfN = N >> 1;
    #pragma unroll
    for (int i = 0; i < TM; i++) {
        const int r = row_c + ty + i;
        #pragma unroll
        for (int j = 0; j < TN; j++) {
            const int c = col_c + tx + j;
            float v = acc[i][j] + bias[c];
            if (mode == 0) {
                C0[(size_t)r * N + c] = v;
            } else {
                if (c < halfN) {
                    C0[(size_t)r * halfN + c] = v;
                } else {
                    float s = v / (1.0f + expf(-v));   // silu
                    C1[(size_t)r * halfN + (c - halfN)] = s;
                }
            }
        }
    }
}

// ---------------- depthwise causal conv (K=4) + SiLU ----------------
__global__ void conv_silu_kernel(const float* __restrict__ w,
                                 const float* __restrict__ cb)
{
    int idx = blockIdx.x * blockDim.x + threadIdx.x;
    if (idx >= Y_ELEMS) return;
    int d = idx & (DD - 1);
    int l = (idx >> 10) & (LL - 1);
    int b = idx >> 22;
    const float* base = g_xssm + ((size_t)b * LL) * DD + d;
    float acc = cb[d];
    #pragma unroll
    for (int k = 0; k < KK; k++) {
        int ll = l - (KK - 1) + k;
        if (ll >= 0) acc = fmaf(base[(size_t)ll * DD], w[d * KK + k], acc);
    }
    g_xconv[idx] = acc / (1.0f + expf(-acc));  // silu
}

// ---------------- BC = x_conv @ W_x + b_x  -> split B,C ----------------
__global__ __launch_bounds__(256)
void bc_gemm_kernel(const float* __restrict__ Wx, const float* __restrict__ bx)
{
    __shared__ float rows[8][DD];
    const int r0 = blockIdx.x * 8;
    const float* src = g_xconv + (size_t)r0 * DD;
    for (int i = threadIdx.x; i < 8 * DD / 4; i += 256)
        ((float4*)&rows[0][0])[i] = ((const float4*)src)[i];
    __syncthreads();

    const int warp = threadIdx.x >> 5;
    const int lane = threadIdx.x & 31;
    const float* row = rows[warp];
    float a0 = 0.f, a1 = 0.f, a2 = 0.f, a3 = 0.f;
    #pragma unroll 4
    for (int k = 0; k < DD; k += 4) {
        a0 = fmaf(row[k + 0], Wx[(k + 0) * 32 + lane], a0);
        a1 = fmaf(row[k + 1], Wx[(k + 1) * 32 + lane], a1);
        a2 = fmaf(row[k + 2], Wx[(k + 2) * 32 + lane], a2);
        a3 = fmaf(row[k + 3], Wx[(k + 3) * 32 + lane], a3);
    }
    float acc = (a0 + a1) + (a2 + a3) + bx[lane];
    const int r = r0 + warp;
    if (lane < NN) g_B[r * NN + lane] = acc;
    else           g_C[r * NN + (lane - NN)] = acc;
}

// ---------------- selective scan + gate multiply ----------------
// block: 256 threads = 8 warps = 16 half-warps; half-warp = one (b,d) pair,
// lane-in-half = state index n. Grid: 128 blocks (2 b x 64 d-groups of 16).
__global__ __launch_bounds__(256)
void scan_kernel(const float* __restrict__ A_log, const float* __restrict__ Dp,
                 float* __restrict__ fstate)
{
    const int b  = blockIdx.x >> 6;
    const int d0 = (blockIdx.x & 63) * 16;
    const int tid  = threadIdx.x;
    const int lane = tid & 31;
    const int wid  = tid >> 5;
    const int half = lane >> 4;
    const int n    = lane & 15;
    const int p    = wid * 2 + half;   // 0..15 local d
    const int d    = d0 + p;

    const float Adn = expf(-expf(A_log[d * NN + n]));
    const float Dd  = Dp[d];

    __shared__ float xc_sm[64][16];
    __shared__ float B_sm[64][16];
    __shared__ float C_sm[64][16];
    __shared__ float y_sm[64][16];

    const size_t bLD = (size_t)b * LL * DD;
    const float* xcp = g_xconv + bLD + d0;
    const float* gp  = g_gate  + bLD + d0;
    float*       yp  = g_yg    + bLD + d0;
    const float* Bp  = g_B + (size_t)b * LL * NN;
    const float* Cp  = g_C + (size_t)b * LL * NN;

    float h = 0.0f;
    for (int t0 = 0; t0 < LL; t0 += 64) {
        for (int i = tid; i < 1024; i += 256) {
            int tl = i >> 4, dl = i & 15;
            xc_sm[tl][dl] = xcp[(size_t)(t0 + tl) * DD + dl];
            B_sm[tl][dl]  = Bp[(t0 + tl) * NN + dl];
            C_sm[tl][dl]  = Cp[(t0 + tl) * NN + dl];
        }
        __syncthreads();
        #pragma unroll 4
        for (int tl = 0; tl < 64; tl++) {
            float xc = xc_sm[tl][p];
            float bv = B_sm[tl][n];
            float cv = C_sm[tl][n];
            h = fmaf(Adn, h, xc * bv);
            float prod = cv * h;
            prod += __shfl_xor_sync(0xffffffffu, prod, 8, 16);
            prod += __shfl_xor_sync(0xffffffffu, prod, 4, 16);
            prod += __shfl_xor_sync(0xffffffffu, prod, 2, 16);
            prod += __shfl_xor_sync(0xffffffffu, prod, 1, 16);
            if (n == 0) y_sm[tl][p] = fmaf(Dd, xc, prod);
        }
        __syncthreads();
        for (int i = tid; i < 1024; i += 256) {
            int tl = i >> 4, dl = i & 15;
            size_t gi = (size_t)(t0 + tl) * DD + dl;
            yp[gi] = y_sm[tl][dl] * gp[gi];
        }
        __syncthreads();
    }
    // final_state[b][n] = mean over d of h
    atomicAdd(&fstate[b * NN + n], h * (1.0f / (float)DD));
}

__global__ void zero_tail_kernel(float* p)
{
    if (threadIdx.x < BB * NN) p[threadIdx.x] = 0.0f;
}

// ---------------- launcher ----------------
extern "C" void kernel_launch(void* const* d_in, const int* in_sizes, int n_in,
                              void* d_out, int out_size)
{
    const float* x      = (const float*)d_in[0];
    const float* W_in   = (const float*)d_in[1];
    const float* b_in   = (const float*)d_in[2];
    const float* conv_w = (const float*)d_in[3];
    const float* conv_b = (const float*)d_in[4];
    const float* W_x    = (const float*)d_in[5];
    const float* b_x    = (const float*)d_in[6];
    const float* A_log  = (const float*)d_in[7];
    const float* D_par  = (const float*)d_in[8];
    const float* W_out  = (const float*)d_in[9];
    const float* b_out  = (const float*)d_in[10];
    float* out = (float*)d_out;

    void *p_xssm, *p_gate, *p_yg;
    cudaGetSymbolAddress(&p_xssm, g_xssm);
    cudaGetSymbolAddress(&p_gate, g_gate);
    cudaGetSymbolAddress(&p_yg,   g_yg);

    // 0) zero final_state tail
    zero_tail_kernel<<<1, 32>>>(out + Y_ELEMS);

    // 1) GEMM1: [8192,1024]@[1024,2048] + b_in -> split (x_ssm raw, silu(gate))
    {
        dim3 grid(2 * DD / BN, MROWS / BM);
        sgemm_kernel<<<grid, 256>>>(x, W_in, b_in,
                                    (float*)p_xssm, (float*)p_gate,
                                    MROWS, 2 * DD, DD, 1);
    }

    // 2) depthwise causal conv + silu
    conv_silu_kernel<<<Y_ELEMS / 256, 256>>>(conv_w, conv_b);

    // 3) BC projection
    bc_gemm_kernel<<<MROWS / 8, 256>>>(W_x, b_x);

    // 4) selective scan + gate multiply + final_state
    scan_kernel<<<BB * (DD / 16), 256>>>(A_log, D_par, out + Y_ELEMS);

    // 5) GEMM2: [8192,1024]@[1024,1024] + b_out -> y output
    {
        dim3 grid(DD / BN, MROWS / BM);
        sgemm_kernel<<<grid, 256>>>((const float*)p_yg, W_out, b_out,
                                    out, nullptr,
                                    MROWS, DD, DD, 0);
    }
}

// round 2
// speedup vs baseline: 1.8235x; 1.8235x over previous
#include <cuda_runtime.h>
#include <cuda_bf16.h>
#include <math.h>
#include <stdint.h>

// ---------------- problem dims ----------------
#define BB 2
#define LL 4096
#define DD 1024
#define NN 16
#define KK 4
#define MROWS (BB*LL)          // 8192
#define Y_ELEMS (BB*LL*DD)     // 8388608

// ---------------- scratch ----------------
__device__ float g_xssm[Y_ELEMS];
__device__ float g_gate[Y_ELEMS];   // silu(gate)
__device__ float g_xconv[Y_ELEMS];
__device__ float g_yg[Y_ELEMS];     // y * silu(gate)
__device__ float g_B[BB*LL*NN];
__device__ float g_C[BB*LL*NN];

// =================== tf32 tensor-core GEMM ===================
// C = A[M,K] @ B[K,N] + bias ; mode 0: plain; mode 1: split halves -> (raw, silu)
#define GBM 128
#define GBN 128
#define GBK 16
#define APAD 4   // As stride GBK+4 = 20 -> conflict-free frag loads
#define BPAD 8   // Bs stride GBN+8 = 136 -> conflict-free frag loads

__device__ __forceinline__ uint32_t f2tf(float f) {
    uint32_t r; asm("cvt.rna.tf32.f32 %0, %1;" : "=r"(r) : "f"(f)); return r;
}
__device__ __forceinline__ void cpasync16(void* dst, const void* src) {
    uint32_t s = (uint32_t)__cvta_generic_to_shared(dst);
    asm volatile("cp.async.cg.shared.global [%0], [%1], 16;\n" :: "r"(s), "l"(src));
}

__global__ __launch_bounds__(256)
void tc_gemm_kernel(const float* __restrict__ A, const float* __restrict__ Bm,
                    const float* __restrict__ bias,
                    float* __restrict__ C0, float* __restrict__ C1,
                    int M, int N, int K, int mode)
{
    __shared__ float As[2][GBM][GBK + APAD];
    __shared__ float Bs[2][GBK][GBN + BPAD];

    const int tid  = threadIdx.x;
    const int lane = tid & 31;
    const int wid  = tid >> 5;
    const int wm   = wid >> 2;          // 0..1 -> m offset wm*64
    const int wn   = wid & 3;           // 0..3 -> n offset wn*32
    const int row_c = blockIdx.y * GBM;
    const int col_c = blockIdx.x * GBN;
    const int r  = lane >> 2;           // 0..7
    const int cq = lane & 3;            // 0..3

    float acc[4][4][4];
    #pragma unroll
    for (int i = 0; i < 4; i++)
        #pragma unroll
        for (int j = 0; j < 4; j++)
            #pragma unroll
            for (int v = 0; v < 4; v++) acc[i][j][v] = 0.0f;

    // prefetch one GBK chunk into buffer `buf`
    auto prefetch = [&](int k0, int buf) {
        #pragma unroll
        for (int s = 0; s < 2; s++) {
            int idx = tid + s * 256;
            // A: 128 rows x 16 cols = 512 float4
            int ar = idx >> 2;
            int ac = (idx & 3) * 4;
            cpasync16(&As[buf][ar][ac],
                      A + (size_t)(row_c + ar) * K + k0 + ac);
            // B: 16 rows x 128 cols = 512 float4
            int br = idx >> 5;
            int bc = (idx & 31) * 4;
            cpasync16(&Bs[buf][br][bc],
                      Bm + (size_t)(k0 + br) * N + col_c + bc);
        }
        asm volatile("cp.async.commit_group;");
    };

    const int nchunks = K / GBK;
    int buf = 0;
    prefetch(0, 0);

    for (int ch = 0; ch < nchunks; ch++) {
        asm volatile("cp.async.wait_group 0;");
        __syncthreads();
        if (ch + 1 < nchunks) prefetch((ch + 1) * GBK, buf ^ 1);

        #pragma unroll
        for (int ks = 0; ks < GBK / 8; ks++) {
            uint32_t af[4][4], bf[4][2];
            #pragma unroll
            for (int mi = 0; mi < 4; mi++) {
                int row = wm * 64 + mi * 16 + r;
                int c   = ks * 8 + cq;
                af[mi][0] = f2tf(As[buf][row][c]);
                af[mi][1] = f2tf(As[buf][row + 8][c]);
                af[mi][2] = f2tf(As[buf][row][c + 4]);
                af[mi][3] = f2tf(As[buf][row + 8][c + 4]);
            }
            #pragma unroll
            for (int ni = 0; ni < 4; ni++) {
                int col = wn * 32 + ni * 8 + r;
                int kr  = ks * 8 + cq;
                bf[ni][0] = f2tf(Bs[buf][kr][col]);
                bf[ni][1] = f2tf(Bs[buf][kr + 4][col]);
            }
            #pragma unroll
            for (int mi = 0; mi < 4; mi++)
                #pragma unroll
                for (int ni = 0; ni < 4; ni++) {
                    asm volatile(
                        "mma.sync.aligned.m16n8k8.row.col.f32.tf32.tf32.f32 "
                        "{%0,%1,%2,%3}, {%4,%5,%6,%7}, {%8,%9}, {%0,%1,%2,%3};"
                        : "+f"(acc[mi][ni][0]), "+f"(acc[mi][ni][1]),
                          "+f"(acc[mi][ni][2]), "+f"(acc[mi][ni][3])
                        : "r"(af[mi][0]), "r"(af[mi][1]),
                          "r"(af[mi][2]), "r"(af[mi][3]),
                          "r"(bf[ni][0]), "r"(bf[ni][1]));
                }
        }
        buf ^= 1;
    }

    // epilogue
    const int halfN = N >> 1;
    #pragma unroll
    for (int mi = 0; mi < 4; mi++) {
        #pragma unroll
        for (int ni = 0; ni < 4; ni++) {
            int r0   = row_c + wm * 64 + mi * 16 + r;
            int col0 = col_c + wn * 32 + ni * 8 + cq * 2;
            #pragma unroll
            for (int v = 0; v < 4; v++) {
                int rr = r0 + (v >> 1) * 8;
                int cc = col0 + (v & 1);
                float val = acc[mi][ni][v] + bias[cc];
                if (mode == 0) {
                    C0[(size_t)rr * N + cc] = val;
                } else {
                    if (cc < halfN) {
                        C0[(size_t)rr * halfN + cc] = val;
                    } else {
                        float sv = val / (1.0f + expf(-val));
                        C1[(size_t)rr * halfN + (cc - halfN)] = sv;
                    }
                }
            }
        }
    }
}

// ---------------- depthwise causal conv (K=4) + SiLU ----------------
__global__ void conv_silu_kernel(const float* __restrict__ w,
                                 const float* __restrict__ cb)
{
    int idx = blockIdx.x * blockDim.x + threadIdx.x;
    if (idx >= Y_ELEMS) return;
    int d = idx & (DD - 1);
    int l = (idx >> 10) & (LL - 1);
    int b = idx >> 22;
    const float* base = g_xssm + ((size_t)b * LL) * DD + d;
    float acc = cb[d];
    #pragma unroll
    for (int k = 0; k < KK; k++) {
        int ll = l - (KK - 1) + k;
        if (ll >= 0) acc = fmaf(base[(size_t)ll * DD], w[d * KK + k], acc);
    }
    g_xconv[idx] = acc / (1.0f + expf(-acc));  // silu
}

// ---------------- BC = x_conv @ W_x + b_x -> split B,C ----------------
__global__ __launch_bounds__(256)
void bc_gemm_kernel(const float* __restrict__ Wx, const float* __restrict__ bx)
{
    __shared__ float rows[8][DD];
    const int r0 = blockIdx.x * 8;
    const float* src = g_xconv + (size_t)r0 * DD;
    for (int i = threadIdx.x; i < 8 * DD / 4; i += 256)
        ((float4*)&rows[0][0])[i] = ((const float4*)src)[i];
    __syncthreads();

    const int warp = threadIdx.x >> 5;
    const int lane = threadIdx.x & 31;
    const float* row = rows[warp];
    float a0 = 0.f, a1 = 0.f, a2 = 0.f, a3 = 0.f;
    #pragma unroll 4
    for (int k = 0; k < DD; k += 4) {
        a0 = fmaf(row[k + 0], Wx[(k + 0) * 32 + lane], a0);
        a1 = fmaf(row[k + 1], Wx[(k + 1) * 32 + lane], a1);
        a2 = fmaf(row[k + 2], Wx[(k + 2) * 32 + lane], a2);
        a3 = fmaf(row[k + 3], Wx[(k + 3) * 32 + lane], a3);
    }
    float acc = (a0 + a1) + (a2 + a3) + bx[lane];
    const int r = r0 + warp;
    if (lane < NN) g_B[r * NN + lane] = acc;
    else           g_C[r * NN + (lane - NN)] = acc;
}

// ---------------- selective scan + gate multiply ----------------
__global__ __launch_bounds__(256)
void scan_kernel(const float* __restrict__ A_log, const float* __restrict__ Dp,
                 float* __restrict__ fstate)
{
    const int b  = blockIdx.x >> 6;
    const int d0 = (blockIdx.x & 63) * 16;
    const int tid  = threadIdx.x;
    const int lane = tid & 31;
    const int wid  = tid >> 5;
    const int half = lane >> 4;
    const int n    = lane & 15;
    const int p    = wid * 2 + half;   // 0..15 local d
    const int d    = d0 + p;

    const float Adn = expf(-expf(A_log[d * NN + n]));
    const float Dd  = Dp[d];

    __shared__ float xc_sm[64][16];
    __shared__ float B_sm[64][16];
    __shared__ float C_sm[64][16];
    __shared__ float y_sm[64][16];

    const size_t bLD = (size_t)b * LL * DD;
    const float* xcp = g_xconv + bLD + d0;
    const float* gp  = g_gate  + bLD + d0;
    float*       yp  = g_yg    + bLD + d0;
    const float* Bp  = g_B + (size_t)b * LL * NN;
    const float* Cp  = g_C + (size_t)b * LL * NN;

    float h = 0.0f;
    for (int t0 = 0; t0 < LL; t0 += 64) {
        for (int i = tid; i < 1024; i += 256) {
            int tl = i >> 4, dl = i & 15;
            xc_sm[tl][dl] = xcp[(size_t)(t0 + tl) * DD + dl];
            B_sm[tl][dl]  = Bp[(t0 + tl) * NN + dl];
            C_sm[tl][dl]  = Cp[(t0 + tl) * NN + dl];
        }
        __syncthreads();
        #pragma unroll 4
        for (int tl = 0; tl < 64; tl++) {
            float xc = xc_sm[tl][p];
            float bv = B_sm[tl][n];
            float cv = C_sm[tl][n];
            h = fmaf(Adn, h, xc * bv);
            float prod = cv * h;
            prod += __shfl_xor_sync(0xffffffffu, prod, 8, 16);
            prod += __shfl_xor_sync(0xffffffffu, prod, 4, 16);
            prod += __shfl_xor_sync(0xffffffffu, prod, 2, 16);
            prod += __shfl_xor_sync(0xffffffffu, prod, 1, 16);
            if (n == 0) y_sm[tl][p] = fmaf(Dd, xc, prod);
        }
        __syncthreads();
        for (int i = tid; i < 1024; i += 256) {
            int tl = i >> 4, dl = i & 15;
            size_t gi = (size_t)(t0 + tl) * DD + dl;
            yp[gi] = y_sm[tl][dl] * gp[gi];
        }
        __syncthreads();
    }
    atomicAdd(&fstate[b * NN + n], h * (1.0f / (float)DD));
}

__global__ void zero_tail_kernel(float* p)
{
    if (threadIdx.x < BB * NN) p[threadIdx.x] = 0.0f;
}

// ---------------- launcher ----------------
extern "C" void kernel_launch(void* const* d_in, const int* in_sizes, int n_in,
                              void* d_out, int out_size)
{
    const float* x      = (const float*)d_in[0];
    const float* W_in   = (const float*)d_in[1];
    const float* b_in   = (const float*)d_in[2];
    const float* conv_w = (const float*)d_in[3];
    const float* conv_b = (const float*)d_in[4];
    const float* W_x    = (const float*)d_in[5];
    const float* b_x    = (const float*)d_in[6];
    const float* A_log  = (const float*)d_in[7];
    const float* D_par  = (const float*)d_in[8];
    const float* W_out  = (const float*)d_in[9];
    const float* b_out  = (const float*)d_in[10];
    float* out = (float*)d_out;

    void *p_xssm, *p_gate, *p_yg;
    cudaGetSymbolAddress(&p_xssm, g_xssm);
    cudaGetSymbolAddress(&p_gate, g_gate);
    cudaGetSymbolAddress(&p_yg,   g_yg);

    // 0) zero final_state tail
    zero_tail_kernel<<<1, 32>>>(out + Y_ELEMS);

    // 1) GEMM1 (tf32 tensor cores): [8192,1024]@[1024,2048] -> split
    {
        dim3 grid(2 * DD / GBN, MROWS / GBM);
        tc_gemm_kernel<<<grid, 256>>>(x, W_in, b_in,
                                      (float*)p_xssm, (float*)p_gate,
                                      MROWS, 2 * DD, DD, 1);
    }

    // 2) depthwise causal conv + silu
    conv_silu_kernel<<<Y_ELEMS / 256, 256>>>(conv_w, conv_b);

    // 3) BC projection
    bc_gemm_kernel<<<MROWS / 8, 256>>>(W_x, b_x);

    // 4) selective scan + gate multiply + final_state
    scan_kernel<<<BB * (DD / 16), 256>>>(A_log, D_par, out + Y_ELEMS);

    // 5) GEMM2 (tf32 tensor cores): [8192,1024]@[1024,1024]
    {
        dim3 grid(DD / GBN, MROWS / GBM);
        tc_gemm_kernel<<<grid, 256>>>((const float*)p_yg, W_out, b_out,
                                      out, nullptr,
                                      MROWS, DD, DD, 0);
    }
}

// round 3
// speedup vs baseline: 3.6380x; 1.9950x over previous
#include <cuda_runtime.h>
#include <cuda_bf16.h>
#include <math.h>
#include <stdint.h>

// ---------------- problem dims ----------------
#define BB 2
#define LL 4096
#define DD 1024
#define NN 16
#define KK 4
#define SEG 32
#define TSEG 128            // LL/SEG
#define MROWS (BB*LL)       // 8192
#define Y_ELEMS (BB*LL*DD)  // 8388608

// ---------------- scratch ----------------
__device__ float g_xssm[Y_ELEMS];
__device__ float g_gate[Y_ELEMS];    // silu(gate)
__device__ float g_xconv[Y_ELEMS];
__device__ float g_yg[Y_ELEMS];      // y*silu(gate), tf32-rounded
__device__ float g_B[BB*LL*NN];
__device__ float g_C[BB*LL*NN];
__device__ float g_xr[Y_ELEMS];      // tf32-rounded x
__device__ float g_wr[DD*2*DD];      // tf32-rounded W_in
__device__ float g_wor[DD*DD];       // tf32-rounded W_out
__device__ float g_hseg[BB*SEG*NN*DD];  // per-seg local end states
__device__ float g_h0[BB*SEG*NN*DD];    // per-seg init states

__device__ __forceinline__ float rtf(float f) {
    uint32_t r; asm("cvt.rna.tf32.f32 %0, %1;" : "=r"(r) : "f"(f));
    return __uint_as_float(r);
}

// ---------------- tf32 pre-round ----------------
__global__ void round_tf32_kernel(const float* __restrict__ src,
                                  float* __restrict__ dst, int n4)
{
    int i = blockIdx.x * blockDim.x + threadIdx.x;
    if (i >= n4) return;
    float4 v = ((const float4*)src)[i];
    v.x = rtf(v.x); v.y = rtf(v.y); v.z = rtf(v.z); v.w = rtf(v.w);
    ((float4*)dst)[i] = v;
}

// =================== tf32 tensor-core GEMM (3-stage) ===================
#define GBM 128
#define GBN 128
#define GBK 16
#define APAD 4
#define BPAD 8
#define ASTRIDE (GBK+APAD)          // 20
#define BSTRIDE (GBN+BPAD)          // 136
#define A_STG (GBM*ASTRIDE)         // 2560
#define B_STG (GBK*BSTRIDE)         // 2176
#define STAGES 3
#define GEMM_SMEM (STAGES*(A_STG+B_STG)*4)  // 56832 bytes

__device__ __forceinline__ void cpasync16(void* dst, const void* src) {
    uint32_t s = (uint32_t)__cvta_generic_to_shared(dst);
    asm volatile("cp.async.cg.shared.global [%0], [%1], 16;\n" :: "r"(s), "l"(src));
}

__global__ __launch_bounds__(256)
void tc_gemm_kernel(const float* __restrict__ A, const float* __restrict__ Bm,
                    const float* __restrict__ bias,
                    float* __restrict__ C0, float* __restrict__ C1,
                    int M, int N, int K, int mode)
{
    extern __shared__ float sm[];
    float* As_ = sm;                    // [STAGES][GBM][ASTRIDE]
    float* Bs_ = sm + STAGES * A_STG;   // [STAGES][GBK][BSTRIDE]

    const int tid  = threadIdx.x;
    const int lane = tid & 31;
    const int wid  = tid >> 5;
    const int wm   = wid >> 2;
    const int wn   = wid & 3;
    const int row_c = blockIdx.y * GBM;
    const int col_c = blockIdx.x * GBN;
    const int r  = lane >> 2;
    const int cq = lane & 3;

    float acc[4][4][4];
    #pragma unroll
    for (int i = 0; i < 4; i++)
        #pragma unroll
        for (int j = 0; j < 4; j++)
            #pragma unroll
            for (int v = 0; v < 4; v++) acc[i][j][v] = 0.0f;

    const int a_row0 = tid >> 2;
    const int a_col0 = (tid & 3) * 4;
    const int b_row0 = tid >> 5;
    const int b_col0 = (tid & 31) * 4;

    auto prefetch = [&](int k0, int st) {
        float* Asb = As_ + st * A_STG;
        float* Bsb = Bs_ + st * B_STG;
        #pragma unroll
        for (int s = 0; s < 2; s++) {
            int ar = a_row0 + s * 64;
            cpasync16(&Asb[ar * ASTRIDE + a_col0],
                      A + (size_t)(row_c + ar) * K + k0 + a_col0);
            int br = b_row0 + s * 8;
            cpasync16(&Bsb[br * BSTRIDE + b_col0],
                      Bm + (size_t)(k0 + br) * N + col_c + b_col0);
        }
        asm volatile("cp.async.commit_group;");
    };

    const int nchunks = K / GBK;   // 64
    prefetch(0, 0);
    prefetch(GBK, 1);

    for (int ch = 0; ch < nchunks; ch++) {
        if (ch >= nchunks - 2) asm volatile("cp.async.wait_group 0;");
        else                   asm volatile("cp.async.wait_group 1;");
        __syncthreads();
        if (ch + 2 < nchunks) prefetch((ch + 2) * GBK, (ch + 2) % STAGES);

        const float* Asb = As_ + (ch % STAGES) * A_STG;
        const float* Bsb = Bs_ + (ch % STAGES) * B_STG;

        #pragma unroll
        for (int ks = 0; ks < GBK / 8; ks++) {
            uint32_t af[4][4], bf[4][2];
            #pragma unroll
            for (int mi = 0; mi < 4; mi++) {
                int row = wm * 64 + mi * 16 + r;
                int c   = ks * 8 + cq;
                af[mi][0] = __float_as_uint(Asb[row * ASTRIDE + c]);
                af[mi][1] = __float_as_uint(Asb[(row + 8) * ASTRIDE + c]);
                af[mi][2] = __float_as_uint(Asb[row * ASTRIDE + c + 4]);
                af[mi][3] = __float_as_uint(Asb[(row + 8) * ASTRIDE + c + 4]);
            }
            #pragma unroll
            for (int ni = 0; ni < 4; ni++) {
                int col = wn * 32 + ni * 8 + r;
                int kr  = ks * 8 + cq;
                bf[ni][0] = __float_as_uint(Bsb[kr * BSTRIDE + col]);
                bf[ni][1] = __float_as_uint(Bsb[(kr + 4) * BSTRIDE + col]);
            }
            #pragma unroll
            for (int mi = 0; mi < 4; mi++)
                #pragma unroll
                for (int ni = 0; ni < 4; ni++) {
                    asm volatile(
                        "mma.sync.aligned.m16n8k8.row.col.f32.tf32.tf32.f32 "
                        "{%0,%1,%2,%3}, {%4,%5,%6,%7}, {%8,%9}, {%0,%1,%2,%3};"
                        : "+f"(acc[mi][ni][0]), "+f"(acc[mi][ni][1]),
                          "+f"(acc[mi][ni][2]), "+f"(acc[mi][ni][3])
                        : "r"(af[mi][0]), "r"(af[mi][1]),
                          "r"(af[mi][2]), "r"(af[mi][3]),
                          "r"(bf[ni][0]), "r"(bf[ni][1]));
                }
        }
        __syncthreads();
    }

    const int halfN = N >> 1;
    #pragma unroll
    for (int mi = 0; mi < 4; mi++) {
        #pragma unroll
        for (int ni = 0; ni < 4; ni++) {
            int r0   = row_c + wm * 64 + mi * 16 + r;
            int col0 = col_c + wn * 32 + ni * 8 + cq * 2;
            #pragma unroll
            for (int v = 0; v < 4; v++) {
                int rr = r0 + (v >> 1) * 8;
                int cc = col0 + (v & 1);
                float val = acc[mi][ni][v] + bias[cc];
                if (mode == 0) {
                    C0[(size_t)rr * N + cc] = val;
                } else {
                    if (cc < halfN) {
                        C0[(size_t)rr * halfN + cc] = val;
                    } else {
                        float sv = val / (1.0f + expf(-val));
                        C1[(size_t)rr * halfN + (cc - halfN)] = sv;
                    }
                }
            }
        }
    }
}

// ---------------- depthwise causal conv (K=4) + SiLU (4 l per thread) ----
__global__ void conv_silu_kernel(const float* __restrict__ w,
                                 const float* __restrict__ cb)
{
    int idx = blockIdx.x * blockDim.x + threadIdx.x;   // Y_ELEMS/4 threads
    if (idx >= Y_ELEMS / 4) return;
    int d  = idx & (DD - 1);
    int lq = (idx >> 10) & (LL / 4 - 1);
    int b  = idx >> 20;
    int l0 = lq * 4;
    const float* base = g_xssm + (size_t)b * LL * DD + d;
    float w0 = w[d * KK + 0], w1 = w[d * KK + 1],
          w2 = w[d * KK + 2], w3 = w[d * KK + 3];
    float bias = cb[d];
    float xm3 = (l0 >= 3) ? base[(size_t)(l0 - 3) * DD] : 0.0f;
    float xm2 = (l0 >= 2) ? base[(size_t)(l0 - 2) * DD] : 0.0f;
    float xm1 = (l0 >= 1) ? base[(size_t)(l0 - 1) * DD] : 0.0f;
    float x0 = base[(size_t)(l0 + 0) * DD];
    float x1 = base[(size_t)(l0 + 1) * DD];
    float x2 = base[(size_t)(l0 + 2) * DD];
    float x3 = base[(size_t)(l0 + 3) * DD];
    float* outp = g_xconv + (size_t)b * LL * DD + d;
    float v;
    v = bias + w0*xm3 + w1*xm2 + w2*xm1 + w3*x0;
    outp[(size_t)(l0+0)*DD] = v / (1.0f + expf(-v));
    v = bias + w0*xm2 + w1*xm1 + w2*x0 + w3*x1;
    outp[(size_t)(l0+1)*DD] = v / (1.0f + expf(-v));
    v = bias + w0*xm1 + w1*x0 + w2*x1 + w3*x2;
    outp[(size_t)(l0+2)*DD] = v / (1.0f + expf(-v));
    v = bias + w0*x0 + w1*x1 + w2*x2 + w3*x3;
    outp[(size_t)(l0+3)*DD] = v / (1.0f + expf(-v));
}

// ---------------- BC = x_conv @ W_x + b_x (W staged in smem once) --------
#define BC_SMEM (DD*32*4 + 8*DD*4 + 8*8*32*4)   // 131072+32768+8192 = 172032

__global__ __launch_bounds__(256)
void bc_kernel(const float* __restrict__ Wx, const float* __restrict__ bx)
{
    extern __shared__ float sm[];
    float* Wsm  = sm;                 // [1024][32]
    float* rows = sm + DD * 32;       // [8][1024]
    float* psum = rows + 8 * DD;      // [8][8][32]

    const int tid = threadIdx.x;
    const int c   = tid & 31;
    const int ks  = tid >> 5;         // 0..7  (k-slice of 128)
    const int r0  = blockIdx.x * 64;

    for (int i = tid; i < DD * 32 / 4; i += 256)
        ((float4*)Wsm)[i] = ((const float4*)Wx)[i];
    __syncthreads();

    for (int g = 0; g < 8; g++) {
        const float* src = g_xconv + (size_t)(r0 + g * 8) * DD;
        for (int i = tid; i < 8 * DD / 4; i += 256)
            ((float4*)rows)[i] = ((const float4*)src)[i];
        __syncthreads();

        float acc[8];
        #pragma unroll
        for (int rr = 0; rr < 8; rr++) acc[rr] = 0.0f;

        const int kbase = ks * 128;
        for (int k4 = 0; k4 < 128; k4 += 4) {
            int k = kbase + k4;
            float w0 = Wsm[(k + 0) * 32 + c];
            float w1 = Wsm[(k + 1) * 32 + c];
            float w2 = Wsm[(k + 2) * 32 + c];
            float w3 = Wsm[(k + 3) * 32 + c];
            #pragma unroll
            for (int rr = 0; rr < 8; rr++) {
                float4 xv = *(const float4*)&rows[rr * DD + k];
                acc[rr] = fmaf(xv.x, w0, fmaf(xv.y, w1,
                          fmaf(xv.z, w2, fmaf(xv.w, w3, acc[rr]))));
            }
        }
        #pragma unroll
        for (int rr = 0; rr < 8; rr++)
            psum[(rr * 8 + ks) * 32 + c] = acc[rr];
        __syncthreads();

        {
            int rr = tid >> 5;
            int c2 = tid & 31;
            float s = bx[c2];
            #pragma unroll
            for (int q = 0; q < 8; q++) s += psum[(rr * 8 + q) * 32 + c2];
            int r = r0 + g * 8 + rr;
            if (c2 < NN) g_B[r * NN + c2] = s;
            else         g_C[r * NN + (c2 - NN)] = s;
        }
        __syncthreads();
    }
}

// ---------------- scan pass 1: per-segment local end states ------------
__global__ __launch_bounds__(256)
void scan1_kernel(const float* __restrict__ A_log)
{
    __shared__ float Xsm[32][256];
    __shared__ __align__(16) float Bsm[32][16];

    const int tid = threadIdx.x;
    const int dt  = blockIdx.x & 3;
    const int s   = (blockIdx.x >> 2) & 31;
    const int b   = blockIdx.x >> 7;
    const int d   = dt * 256 + tid;

    float Adn[16];
    #pragma unroll
    for (int n = 0; n < 16; n++) Adn[n] = expf(-expf(A_log[d * NN + n]));

    float h[16];
    #pragma unroll
    for (int n = 0; n < 16; n++) h[n] = 0.0f;

    const float* xcp = g_xconv + (size_t)b * LL * DD + dt * 256;
    const float* Bp  = g_B + (size_t)b * LL * NN;
    const int t0 = s * TSEG;

    for (int cc = 0; cc < 4; cc++) {
        int tb = t0 + cc * 32;
        if (tid < 128)
            ((float4*)Bsm)[tid] = ((const float4*)(Bp + (size_t)tb * NN))[tid];
        #pragma unroll 8
        for (int i = 0; i < 32; i++)
            Xsm[i][tid] = xcp[(size_t)(tb + i) * DD + tid];
        __syncthreads();
        #pragma unroll 4
        for (int tl = 0; tl < 32; tl++) {
            float xc = Xsm[tl][tid];
            float4 b0 = *(const float4*)&Bsm[tl][0];
            float4 b1 = *(const float4*)&Bsm[tl][4];
            float4 b2 = *(const float4*)&Bsm[tl][8];
            float4 b3 = *(const float4*)&Bsm[tl][12];
            h[0]  = fmaf(Adn[0],  h[0],  xc * b0.x);
            h[1]  = fmaf(Adn[1],  h[1],  xc * b0.y);
            h[2]  = fmaf(Adn[2],  h[2],  xc * b0.z);
            h[3]  = fmaf(Adn[3],  h[3],  xc * b0.w);
            h[4]  = fmaf(Adn[4],  h[4],  xc * b1.x);
            h[5]  = fmaf(Adn[5],  h[5],  xc * b1.y);
            h[6]  = fmaf(Adn[6],  h[6],  xc * b1.z);
            h[7]  = fmaf(Adn[7],  h[7],  xc * b1.w);
            h[8]  = fmaf(Adn[8],  h[8],  xc * b2.x);
            h[9]  = fmaf(Adn[9],  h[9],  xc * b2.y);
            h[10] = fmaf(Adn[10], h[10], xc * b2.z);
            h[11] = fmaf(Adn[11], h[11], xc * b2.w);
            h[12] = fmaf(Adn[12], h[12], xc * b3.x);
            h[13] = fmaf(Adn[13], h[13], xc * b3.y);
            h[14] = fmaf(Adn[14], h[14], xc * b3.z);
            h[15] = fmaf(Adn[15], h[15], xc * b3.w);
        }
        __syncthreads();
    }
    #pragma unroll
    for (int n = 0; n < 16; n++)
        g_hseg[((size_t)(b * SEG + s) * NN + n) * DD + d] = h[n];
}

// ---------------- combine: serial prefix over segments + final_state ----
__global__ __launch_bounds__(256)
void combine_kernel(const float* __restrict__ A_log, float* __restrict__ fstate)
{
    int idx = blockIdx.x * 256 + threadIdx.x;   // 32768 threads
    int d = idx & (DD - 1);
    int bn = idx >> 10;
    int n = bn & 15;
    int b = bn >> 4;

    float Adn = expf(-expf(A_log[d * NN + n]));
    float p = Adn;
    #pragma unroll
    for (int i = 0; i < 7; i++) p = p * p;   // Adn^128

    size_t base = ((size_t)(b * SEG) * NN + n) * DD + d;
    const size_t stride = (size_t)NN * DD;
    float h = 0.0f;
    #pragma unroll 4
    for (int s = 0; s < SEG; s++) {
        g_h0[base + s * stride] = h;
        h = fmaf(p, h, g_hseg[base + s * stride]);
    }
    // warp reduce over d (warp shares (b,n))
    #pragma unroll
    for (int off = 16; off >= 1; off >>= 1)
        h += __shfl_xor_sync(0xffffffffu, h, off);
    if ((threadIdx.x & 31) == 0)
        atomicAdd(&fstate[b * NN + n], h * (1.0f / (float)DD));
}

// ---------------- scan pass 2: full recurrence + y + gate ---------------
__global__ __launch_bounds__(256)
void scan2_kernel(const float* __restrict__ A_log, const float* __restrict__ Dp)
{
    __shared__ float Xsm[32][256];
    __shared__ __align__(16) float Bsm[32][16];
    __shared__ __align__(16) float Csm[32][16];

    const int tid = threadIdx.x;
    const int dt  = blockIdx.x & 3;
    const int s   = (blockIdx.x >> 2) & 31;
    const int b   = blockIdx.x >> 7;
    const int d   = dt * 256 + tid;

    float Adn[16];
    #pragma unroll
    for (int n = 0; n < 16; n++) Adn[n] = expf(-expf(A_log[d * NN + n]));
    const float Dd = Dp[d];

    float h[16];
    {
        size_t base = ((size_t)(b * SEG + s) * NN) * DD + d;
        #pragma unroll
        for (int n = 0; n < 16; n++) h[n] = g_h0[base + (size_t)n * DD];
    }

    const float* xcp = g_xconv + (size_t)b * LL * DD + dt * 256;
    const float* gp  = g_gate  + (size_t)b * LL * DD + dt * 256;
    float*       yp  = g_yg    + (size_t)b * LL * DD + dt * 256;
    const float* Bp  = g_B + (size_t)b * LL * NN;
    const float* Cp  = g_C + (size_t)b * LL * NN;
    const int t0 = s * TSEG;

    for (int cc = 0; cc < 4; cc++) {
        int tb = t0 + cc * 32;
        if (tid < 128) {
            ((float4*)Bsm)[tid] = ((const float4*)(Bp + (size_t)tb * NN))[tid];
            ((float4*)Csm)[tid] = ((const float4*)(Cp + (size_t)tb * NN))[tid];
        }
        #pragma unroll 8
        for (int i = 0; i < 32; i++)
            Xsm[i][tid] = xcp[(size_t)(tb + i) * DD + tid];
        __syncthreads();
        #pragma unroll 2
        for (int tl = 0; tl < 32; tl++) {
            float xc = Xsm[tl][tid];
            float4 b0 = *(const float4*)&Bsm[tl][0];
            float4 b1 = *(const float4*)&Bsm[tl][4];
            float4 b2 = *(const float4*)&Bsm[tl][8];
            float4 b3 = *(const float4*)&Bsm[tl][12];
            h[0]  = fmaf(Adn[0],  h[0],  xc * b0.x);
            h[1]  = fmaf(Adn[1],  h[1],  xc * b0.y);
            h[2]  = fmaf(Adn[2],  h[2],  xc * b0.z);
            h[3]  = fmaf(Adn[3],  h[3],  xc * b0.w);
            h[4]  = fmaf(Adn[4],  h[4],  xc * b1.x);
            h[5]  = fmaf(Adn[5],  h[5],  xc * b1.y);
            h[6]  = fmaf(Adn[6],  h[6],  xc * b1.z);
            h[7]  = fmaf(Adn[7],  h[7],  xc * b1.w);
            h[8]  = fmaf(Adn[8],  h[8],  xc * b2.x);
            h[9]  = fmaf(Adn[9],  h[9],  xc * b2.y);
            h[10] = fmaf(Adn[10], h[10], xc * b2.z);
            h[11] = fmaf(Adn[11], h[11], xc * b2.w);
            h[12] = fmaf(Adn[12], h[12], xc * b3.x);
            h[13] = fmaf(Adn[13], h[13], xc * b3.y);
            h[14] = fmaf(Adn[14], h[14], xc * b3.z);
            h[15] = fmaf(Adn[15], h[15], xc * b3.w);
            float4 c0 = *(const float4*)&Csm[tl][0];
            float4 c1 = *(const float4*)&Csm[tl][4];
            float4 c2 = *(const float4*)&Csm[tl][8];
            float4 c3 = *(const float4*)&Csm[tl][12];
            float y0 = fmaf(c0.x, h[0],  fmaf(c0.y, h[1],
                       fmaf(c0.z, h[2],  c0.w * h[3])));
            float y1 = fmaf(c1.x, h[4],  fmaf(c1.y, h[5],
                       fmaf(c1.z, h[6],  c1.w * h[7])));
            float y2 = fmaf(c2.x, h[8],  fmaf(c2.y, h[9],
                       fmaf(c2.z, h[10], c2.w * h[11])));
            float y3 = fmaf(c3.x, h[12], fmaf(c3.y, h[13],
                       fmaf(c3.z, h[14], c3.w * h[15])));
            float y = ((y0 + y1) + (y2 + y3)) + Dd * xc;
            float gv = gp[(size_t)(tb + tl) * DD + tid];
            yp[(size_t)(tb + tl) * DD + tid] = rtf(y * gv);
        }
        __syncthreads();
    }
}

__global__ void zero_tail_kernel(float* p)
{
    if (threadIdx.x < BB * NN) p[threadIdx.x] = 0.0f;
}

// ---------------- launcher ----------------
extern "C" void kernel_launch(void* const* d_in, const int* in_sizes, int n_in,
                              void* d_out, int out_size)
{
    const float* x      = (const float*)d_in[0];
    const float* W_in   = (const float*)d_in[1];
    const float* b_in   = (const float*)d_in[2];
    const float* conv_w = (const float*)d_in[3];
    const float* conv_b = (const float*)d_in[4];
    const float* W_x    = (const float*)d_in[5];
    const float* b_x    = (const float*)d_in[6];
    const float* A_log  = (const float*)d_in[7];
    const float* D_par  = (const float*)d_in[8];
    const float* W_out  = (const float*)d_in[9];
    const float* b_out  = (const float*)d_in[10];
    float* out = (float*)d_out;

    static int attr_done = 0;
    if (!attr_done) {
        cudaFuncSetAttribute(tc_gemm_kernel,
            cudaFuncAttributeMaxDynamicSharedMemorySize, GEMM_SMEM);
        cudaFuncSetAttribute(bc_kernel,
            cudaFuncAttributeMaxDynamicSharedMemorySize, BC_SMEM);
        attr_done = 1;
    }

    void *p_xssm, *p_gate, *p_yg, *p_xr, *p_wr, *p_wor;
    cudaGetSymbolAddress(&p_xssm, g_xssm);
    cudaGetSymbolAddress(&p_gate, g_gate);
    cudaGetSymbolAddress(&p_yg,   g_yg);
    cudaGetSymbolAddress(&p_xr,   g_xr);
    cudaGetSymbolAddress(&p_wr,   g_wr);
    cudaGetSymbolAddress(&p_wor,  g_wor);

    // 0) zero final_state tail
    zero_tail_kernel<<<1, 32>>>(out + Y_ELEMS);

    // 1) pre-round GEMM operands to tf32
    round_tf32_kernel<<<Y_ELEMS/4/256, 256>>>(x, (float*)p_xr, Y_ELEMS/4);
    round_tf32_kernel<<<(DD*2*DD)/4/256, 256>>>(W_in, (float*)p_wr, DD*2*DD/4);
    round_tf32_kernel<<<(DD*DD)/4/256, 256>>>(W_out, (float*)p_wor, DD*DD/4);

    // 2) GEMM1: [8192,1024]@[1024,2048] -> (x_ssm raw, silu(gate))
    {
        dim3 grid(2 * DD / GBN, MROWS / GBM);
        tc_gemm_kernel<<<grid, 256, GEMM_SMEM>>>(
            (const float*)p_xr, (const float*)p_wr, b_in,
            (float*)p_xssm, (float*)p_gate, MROWS, 2 * DD, DD, 1);
    }

    // 3) depthwise causal conv + silu
    conv_silu_kernel<<<Y_ELEMS/4/256, 256>>>(conv_w, conv_b);

    // 4) BC projection (W in smem)
    bc_kernel<<<MROWS/64, 256, BC_SMEM>>>(W_x, b_x);

    // 5) chunked scan
    scan1_kernel<<<BB*SEG*4, 256>>>(A_log);
    combine_kernel<<<BB*NN*DD/256, 256>>>(A_log, out + Y_ELEMS);
    scan2_kernel<<<BB*SEG*4, 256>>>(A_log, D_par);

    // 6) GEMM2: [8192,1024]@[1024,1024] -> y
    {
        dim3 grid(DD / GBN, MROWS / GBM);
        tc_gemm_kernel<<<grid, 256, GEMM_SMEM>>>(
            (const float*)p_yg, (const float*)p_wor, b_out,
            out, nullptr, MROWS, DD, DD, 0);
    }
}